// round 4
// baseline (speedup 1.0000x reference)
#include <cuda_runtime.h>
#include <cstdint>

#define NB 32
#define KB 32
#define TB 128
#define HB 768
#define H2 1536

// Output layout (float32, concat of flattened outputs)
#define OFF_SCORE   0
#define OFF_ENC     1024
#define OFF_MASK    3146752
#define OFF_USE     3150848
#define OFF_IDX     3175424

// Block-range layout inside the mega-kernel (producers at low bids!)
#define B_A0      0          // 96 A-GEMM blocks (12 h-tiles x 8 K-splits)
#define B_U0      96         // 12 u-GEMM blocks
#define B_C       108        // 1 c block
#define B_S0      109        // 128 score blocks
#define B_G0      237        // 3072 big-gather blocks
#define B_SM0     3309       // 32 small-gather blocks
#define GRID_TOT  3341

#define NSPLIT    8          // K-splits for A GEMM (1536/8 = 192)

// Scratch (device globals — allocation is forbidden)
__device__ float    g_part[NSPLIT * NB * HB];   // A-GEMM partials
__device__ float    g_u[NB * HB];
__device__ float    g_c[NB];
__device__ unsigned g_cntA, g_cntU, g_done;

__device__ __forceinline__ unsigned ld_acq(const unsigned* p) {
    unsigned v;
    asm volatile("ld.global.acquire.gpu.u32 %0, [%1];" : "=r"(v) : "l"(p));
    return v;
}

__device__ __forceinline__ void spin_until(const unsigned* cnt, unsigned target) {
    if (threadIdx.x == 0) {
        while (ld_acq(cnt) < target) __nanosleep(64);
    }
    __syncthreads();
}

__global__ void __launch_bounds__(256) mega(
    const float* __restrict__ ctx1,
    const float* __restrict__ tku,
    const float* __restrict__ pe0,
    const float* __restrict__ pe1,
    const int*   __restrict__ pm,
    const int*   __restrict__ ckm,
    const int*   __restrict__ label,
    const int*   __restrict__ pt,
    const float* __restrict__ Wcqk,
    const float* __restrict__ bcqk,
    const float* __restrict__ Wk,
    const float* __restrict__ bk,
    float* __restrict__ out)
{
    __shared__ float As[NB][64];      // 8 KB
    __shared__ float Bs[64][65];      // 16.6 KB

    const int b   = blockIdx.x;
    const int tid = threadIdx.x;

    if (b < B_U0) {
        // ---------------- A-GEMM: part[s][n][h] = cqk[n, ks] . Wcqk[h, ks]
        const int htile = b % 12;
        const int s     = b / 12;
        const int h0    = htile * 64;
        const int j_lo  = s * (H2 / NSPLIT);      // 192-wide K slice

        const int tx  = tid & 63;
        const int tyg = tid >> 6;

        float acc[8];
#pragma unroll
        for (int i = 0; i < 8; i++) acc[i] = 0.f;

        for (int j0 = j_lo; j0 < j_lo + (H2 / NSPLIT); j0 += 64) {
            for (int i = tid; i < NB * 64; i += 256) {
                int n = i >> 6, kk = i & 63;
                int j = j0 + kk;
                As[n][kk] = (j < HB) ? ctx1[n * 3 * HB + 2 * HB + j]
                                     : tku[n * HB + (j - HB)];
            }
            for (int i = tid; i < 64 * 64; i += 256) {
                int hh = i >> 6, kk = i & 63;
                Bs[kk][hh] = Wcqk[(size_t)(h0 + hh) * H2 + j0 + kk];
            }
            __syncthreads();
#pragma unroll 8
            for (int kk = 0; kk < 64; kk++) {
                float bv = Bs[kk][tx];
#pragma unroll
                for (int i = 0; i < 8; i++)
                    acc[i] += As[tyg * 8 + i][kk] * bv;
            }
            __syncthreads();
        }
        float* dst = g_part + (size_t)s * NB * HB;
#pragma unroll
        for (int i = 0; i < 8; i++)
            dst[(size_t)(tyg * 8 + i) * HB + h0 + tx] = acc[i];

        __threadfence();
        __syncthreads();
        if (tid == 0) atomicAdd(&g_cntA, 1u);

    } else if (b < B_C) {
        // ---------------- u-GEMM: u[n,h] = sum_g cqkp[n,g] * Wk[g,h]
        //   cqkp[n,g] = bcqk[g] + sum_s part[s][n][g]   (summed on the fly)
        spin_until(&g_cntA, 96);

        const int h0  = (b - B_U0) * 64;
        const int tx  = tid & 63;
        const int tyg = tid >> 6;

        float acc[8];
#pragma unroll
        for (int i = 0; i < 8; i++) acc[i] = 0.f;

        for (int g0 = 0; g0 < HB; g0 += 64) {
            for (int i = tid; i < NB * 64; i += 256) {
                int n = i >> 6, kk = i & 63;
                int g = g0 + kk;
                float v = bcqk[g];
#pragma unroll
                for (int s = 0; s < NSPLIT; s++)
                    v += g_part[(size_t)s * NB * HB + (size_t)n * HB + g];
                As[n][kk] = v;
            }
            for (int i = tid; i < 64 * 64; i += 256) {
                int kk = i >> 6, hh = i & 63;
                Bs[kk][hh] = Wk[(size_t)(g0 + kk) * HB + h0 + hh];
            }
            __syncthreads();
#pragma unroll 8
            for (int kk = 0; kk < 64; kk++) {
                float bv = Bs[kk][tx];
#pragma unroll
                for (int i = 0; i < 8; i++)
                    acc[i] += As[tyg * 8 + i][kk] * bv;
            }
            __syncthreads();
        }
#pragma unroll
        for (int i = 0; i < 8; i++)
            g_u[(size_t)(tyg * 8 + i) * HB + h0 + tx] = acc[i];

        __threadfence();
        __syncthreads();
        if (tid == 0) atomicAdd(&g_cntU, 1u);

    } else if (b == B_C) {
        // ---------------- c[n] = bk . cqkp[n,:]
        spin_until(&g_cntA, 96);
        const int wid  = tid >> 5;
        const int lane = tid & 31;
#pragma unroll
        for (int r = 0; r < 4; r++) {
            const int n = wid + r * 8;
            float cp = 0.f;
            for (int g0 = 0; g0 < HB; g0 += 32) {
                int g = g0 + lane;
                float v = bcqk[g];
#pragma unroll
                for (int s = 0; s < NSPLIT; s++)
                    v += g_part[(size_t)s * NB * HB + (size_t)n * HB + g];
                cp += bk[g] * v;
            }
#pragma unroll
            for (int o = 16; o; o >>= 1) cp += __shfl_xor_sync(0xFFFFFFFFu, cp, o);
            if (lane == 0) g_c[n] = cp;
        }
        __threadfence();
        __syncthreads();
        if (tid == 0) atomicAdd(&g_cntU, 1u);

    } else if (b < B_G0) {
        // ---------------- score[n,k] = mask ? pe1[n,k,:].u[n,:] + c[n] : -1e20
        spin_until(&g_cntU, 13);

        const int bb   = b - B_S0;
        const int n    = bb >> 2;
        const int kg   = bb & 3;
        const int wid  = tid >> 5;
        const int lane = tid & 31;
        const int k    = kg * 8 + wid;

        const float4* p  = (const float4*)(pe1 + ((size_t)n * KB + k) * HB);
        const float4* uu = (const float4*)(g_u + (size_t)n * HB);
        float sacc = 0.f;
#pragma unroll
        for (int i = 0; i < 6; i++) {
            float4 a = p[i * 32 + lane];
            float4 q = uu[i * 32 + lane];
            sacc += a.x * q.x + a.y * q.y + a.z * q.z + a.w * q.w;
        }
#pragma unroll
        for (int o = 16; o; o >>= 1) sacc += __shfl_xor_sync(0xFFFFFFFFu, sacc, o);
        if (lane == 0)
            out[OFF_SCORE + n * KB + k] =
                (ckm[n * KB + k] != 0) ? (sacc + g_c[n]) : -1e20f;

    } else if (b < B_SM0) {
        // ---------------- big gather: shifted_encoded (12 MB, float4/thread)
        const int flat = (b - B_G0) * 256 + tid;
        const int n = flat / 24576;
        const int i = flat - n * 24576;
        const float4* src = (const float4*)(pe0 + ((size_t)n * KB + label[n]) * (size_t)TB * HB);
        float4* dst = (float4*)(out + OFF_ENC + (size_t)n * TB * HB);
        dst[i] = src[i];

    } else {
        // ---------------- small gathers
        const int n   = b - B_SM0;
        const int lab = label[n];
        const int base = (n * KB + lab) * TB;
        for (int t = tid; t < TB; t += 256) {
            out[OFF_MASK + n * TB + t] = (pm[base + t] != 0) ? 1.f : 0.f;
            out[OFF_IDX  + n * TB + t] = (float)pt[base + t];
        }
        const size_t ub = ((size_t)n * KB + lab) * HB;
        for (int h = tid; h < HB; h += 256)
            out[OFF_USE + n * HB + h] = pe1[ub + h];
    }

    // ---------------- replay-safe counter reset: last block out cleans up
    __syncthreads();
    if (tid == 0) {
        unsigned v = atomicAdd(&g_done, 1u);
        if (v == (unsigned)(gridDim.x - 1)) {
            g_cntA = 0u;
            g_cntU = 0u;
            g_done = 0u;
            __threadfence();
        }
    }
}

extern "C" void kernel_launch(void* const* d_in, const int* in_sizes, int n_in,
                              void* d_out, int out_size)
{
    const float* ctx1 = (const float*)d_in[0];
    const float* tku  = (const float*)d_in[1];
    const float* pe0  = (const float*)d_in[2];
    const float* pe1  = (const float*)d_in[3];
    const int*   pm   = (const int*)d_in[4];
    const int*   ckm  = (const int*)d_in[5];
    const int*   lab  = (const int*)d_in[6];
    const int*   pt   = (const int*)d_in[7];
    const float* Wcqk = (const float*)d_in[8];
    const float* bcqk = (const float*)d_in[9];
    const float* Wk   = (const float*)d_in[10];
    const float* bk   = (const float*)d_in[11];

    mega<<<GRID_TOT, 256>>>(ctx1, tku, pe0, pe1, pm, ckm, lab, pt,
                            Wcqk, bcqk, Wk, bk, (float*)d_out);
}

// round 6
// speedup vs baseline: 2.1024x; 2.1024x over previous
#include <cuda_runtime.h>
#include <cstdint>

#define NB 32
#define KB 32
#define TB 128
#define HB 768
#define H2 1536

// Output layout (float32, concat of flattened outputs)
#define OFF_SCORE   0
#define OFF_ENC     1024
#define OFF_MASK    3146752
#define OFF_USE     3150848
#define OFF_IDX     3175424

// Scratch (device globals — allocation is forbidden)
__device__ float    g_cqk_pro[NB * HB];
__device__ float    g_u[NB * HB];
__device__ float    g_c[NB];
__device__ unsigned g_cntU, g_done;

__device__ __forceinline__ unsigned ld_acq(const unsigned* p) {
    unsigned v;
    asm volatile("ld.global.acquire.gpu.u32 %0, [%1];" : "=r"(v) : "l"(p));
    return v;
}

// ---------------------------------------------------------------------------
// Kernel 1 (768 blocks x 256): cqk_pro[n,h] = cqk[n,:] . W_cqk[h,:] + b_cqk[h]
// Warp -> (4 h, 1 n). Warps are h-group-major / n-minor, so all 8 warps of a
// block stream the SAME 4 W rows -> 8x L1 reuse.
// ---------------------------------------------------------------------------
__global__ void __launch_bounds__(256) k1_agemm(
    const float* __restrict__ ctx1,
    const float* __restrict__ tku,
    const float* __restrict__ Wcqk,
    const float* __restrict__ bcqk,
    float* __restrict__ cqkp)
{
    const int tid  = threadIdx.x;
    const int wid  = tid >> 5;
    const int lane = tid & 31;
    const int gw   = blockIdx.x * 8 + wid;   // 0..6143
    const int hg   = gw >> 5;                // 0..191  (same for whole block)
    const int n    = gw & 31;                // 0..31   (varies across warps)
    const int h0   = hg * 4;

    // A row (cqk[n,:]) : 12 float4 per lane
    float4 a[12];
    const float4* arow0 = (const float4*)(ctx1 + (size_t)n * 3 * HB + 2 * HB);
    const float4* arow1 = (const float4*)(tku  + (size_t)n * HB);
#pragma unroll
    for (int i = 0; i < 6; i++) a[i]     = arow0[i * 32 + lane];
#pragma unroll
    for (int i = 0; i < 6; i++) a[i + 6] = arow1[i * 32 + lane];

    float acc[4];
#pragma unroll
    for (int hh = 0; hh < 4; hh++) {
        const float4* w = (const float4*)(Wcqk + (size_t)(h0 + hh) * H2);
        float s = 0.f;
#pragma unroll
        for (int i = 0; i < 12; i++) {
            float4 wv = w[i * 32 + lane];
            s += a[i].x * wv.x + a[i].y * wv.y + a[i].z * wv.z + a[i].w * wv.w;
        }
        acc[hh] = s;
    }
#pragma unroll
    for (int hh = 0; hh < 4; hh++) {
#pragma unroll
        for (int o = 16; o; o >>= 1)
            acc[hh] += __shfl_xor_sync(0xFFFFFFFFu, acc[hh], o);
    }
    if (lane == 0) {
        float* dst = cqkp + (size_t)n * HB + h0;
        dst[0] = acc[0] + bcqk[h0 + 0];
        dst[1] = acc[1] + bcqk[h0 + 1];
        dst[2] = acc[2] + bcqk[h0 + 2];
        dst[3] = acc[3] + bcqk[h0 + 3];
    }
}

// ---------------------------------------------------------------------------
// Kernel 2 (1025 blocks x 256), everything else in one launch:
//   blocks [0,96):     u[n,h]   (no spin — cqkp ready at launch).
//   block  96:         c[n] = bk . cqkp[n,:]
//   blocks [97,225):   score  (spin until ALL 97 u/c producers done)
//   blocks [225,993):  big gather shifted_encoded (4 float4 per thread)
//   blocks [993,1025): small gathers
// ---------------------------------------------------------------------------
#define B2_U0   0
#define B2_C    96
#define B2_S0   97
#define B2_G0   225
#define B2_SM0  993
#define GRID2   1025
#define N_PROD  (B2_C - B2_U0 + 1)   // 97 producers feed the score stage

__global__ void __launch_bounds__(256) k2_rest(
    const float* __restrict__ cqkp,
    const float* __restrict__ Wk,
    const float* __restrict__ bk,
    const float* __restrict__ pe0,
    const float* __restrict__ pe1,
    const int*   __restrict__ pm,
    const int*   __restrict__ ckm,
    const int*   __restrict__ label,
    const int*   __restrict__ pt,
    float* __restrict__ out)
{
    const int b    = blockIdx.x;
    const int tid  = threadIdx.x;
    const int wid  = tid >> 5;
    const int lane = tid & 31;

    if (b < B2_C) {
        // ---- u-GEMM: warp -> (htile, n); htile constant per block (W reuse)
        const int gw    = b * 8 + wid;        // 0..767
        const int htile = gw >> 5;            // 0..23 (same for whole block)
        const int n     = gw & 31;
        const int h     = htile * 32 + lane;
        const float* wcol = Wk + h;
        const float* cr   = cqkp + (size_t)n * HB;

        float acc0 = 0.f, acc1 = 0.f, acc2 = 0.f, acc3 = 0.f;
        for (int g0 = 0; g0 < HB; g0 += 32) {
            float cg = cr[g0 + lane];
#pragma unroll
            for (int j = 0; j < 32; j += 4) {
                acc0 += __shfl_sync(0xFFFFFFFFu, cg, j + 0) * wcol[(size_t)(g0 + j + 0) * HB];
                acc1 += __shfl_sync(0xFFFFFFFFu, cg, j + 1) * wcol[(size_t)(g0 + j + 1) * HB];
                acc2 += __shfl_sync(0xFFFFFFFFu, cg, j + 2) * wcol[(size_t)(g0 + j + 2) * HB];
                acc3 += __shfl_sync(0xFFFFFFFFu, cg, j + 3) * wcol[(size_t)(g0 + j + 3) * HB];
            }
        }
        g_u[(size_t)n * HB + h] = (acc0 + acc1) + (acc2 + acc3);

        __threadfence();
        __syncthreads();
        if (tid == 0) atomicAdd(&g_cntU, 1u);

    } else if (b == B2_C) {
        // ---- c[n] = bk . cqkp[n,:]
#pragma unroll
        for (int r = 0; r < 4; r++) {
            const int n = wid + r * 8;
            const float4* cc  = (const float4*)(cqkp + (size_t)n * HB);
            const float4* bb4 = (const float4*)bk;
            float s = 0.f;
#pragma unroll
            for (int i = 0; i < 6; i++) {
                float4 x = cc[i * 32 + lane];
                float4 y = bb4[i * 32 + lane];
                s += x.x * y.x + x.y * y.y + x.z * y.z + x.w * y.w;
            }
#pragma unroll
            for (int o = 16; o; o >>= 1) s += __shfl_xor_sync(0xFFFFFFFFu, s, o);
            if (lane == 0) g_c[n] = s;
        }
        __threadfence();
        __syncthreads();
        if (tid == 0) atomicAdd(&g_cntU, 1u);

    } else if (b < B2_G0) {
        // ---- score: spin until all N_PROD producers are done
        if (tid == 0) {
            while (ld_acq(&g_cntU) < (unsigned)N_PROD) __nanosleep(64);
        }
        __syncthreads();

        const int bb = b - B2_S0;
        const int n  = bb >> 2;
        const int kg = bb & 3;
        const int k  = kg * 8 + wid;

        const float4* p  = (const float4*)(pe1 + ((size_t)n * KB + k) * HB);
        const float4* uu = (const float4*)(g_u + (size_t)n * HB);
        float s = 0.f;
#pragma unroll
        for (int i = 0; i < 6; i++) {
            float4 a = p[i * 32 + lane];
            float4 q = uu[i * 32 + lane];
            s += a.x * q.x + a.y * q.y + a.z * q.z + a.w * q.w;
        }
#pragma unroll
        for (int o = 16; o; o >>= 1) s += __shfl_xor_sync(0xFFFFFFFFu, s, o);
        if (lane == 0)
            out[OFF_SCORE + n * KB + k] =
                (ckm[n * KB + k] != 0) ? (s + g_c[n]) : -1e20f;

    } else if (b < B2_SM0) {
        // ---- big gather: 786432 float4; block covers 1024, thread does 4
        const int gb    = b - B2_G0;          // 0..767
        const int n     = gb / 24;            // 24 blocks per n
        const int chunk = gb % 24;
        const float4* src = (const float4*)(pe0 + ((size_t)n * KB + label[n]) * (size_t)TB * HB);
        float4* dst = (float4*)(out + OFF_ENC + (size_t)n * TB * HB);
        const int i0 = chunk * 1024 + tid;
#pragma unroll
        for (int j = 0; j < 4; j++)
            dst[i0 + j * 256] = src[i0 + j * 256];

    } else {
        // ---- small gathers
        const int n    = b - B2_SM0;
        const int lab  = label[n];
        const int base = (n * KB + lab) * TB;
        for (int t = tid; t < TB; t += 256) {
            out[OFF_MASK + n * TB + t] = (pm[base + t] != 0) ? 1.f : 0.f;
            out[OFF_IDX  + n * TB + t] = (float)pt[base + t];
        }
        const size_t ub = ((size_t)n * KB + lab) * HB;
        for (int h = tid; h < HB; h += 256)
            out[OFF_USE + n * HB + h] = pe1[ub + h];
    }

    // ---- replay-safe reset: last block out clears the counters
    __syncthreads();
    if (tid == 0) {
        unsigned v = atomicAdd(&g_done, 1u);
        if (v == (unsigned)(GRID2 - 1)) {
            g_cntU = 0u;
            g_done = 0u;
            __threadfence();
        }
    }
}

extern "C" void kernel_launch(void* const* d_in, const int* in_sizes, int n_in,
                              void* d_out, int out_size)
{
    const float* ctx1 = (const float*)d_in[0];
    const float* tku  = (const float*)d_in[1];
    const float* pe0  = (const float*)d_in[2];
    const float* pe1  = (const float*)d_in[3];
    const int*   pm   = (const int*)d_in[4];
    const int*   ckm  = (const int*)d_in[5];
    const int*   lab  = (const int*)d_in[6];
    const int*   pt   = (const int*)d_in[7];
    const float* Wcqk = (const float*)d_in[8];
    const float* bcqk = (const float*)d_in[9];
    const float* Wk   = (const float*)d_in[10];
    const float* bk   = (const float*)d_in[11];

    float* out = (float*)d_out;

    float* d_cqkp; cudaGetSymbolAddress((void**)&d_cqkp, g_cqk_pro);

    k1_agemm<<<768, 256>>>(ctx1, tku, Wcqk, bcqk, d_cqkp);
    k2_rest<<<GRID2, 256>>>(d_cqkp, Wk, bk, pe0, pe1, pm, ckm, lab, pt, out);
}

// round 7
// speedup vs baseline: 2.3615x; 1.1232x over previous
#include <cuda_runtime.h>
#include <cstdint>

#define NB 32
#define KB 32
#define TB 128
#define HB 768
#define H2 1536

// Output layout (float32, concat of flattened outputs)
#define OFF_SCORE   0
#define OFF_ENC     1024
#define OFF_MASK    3146752
#define OFF_USE     3150848
#define OFF_IDX     3175424

// Scratch (device globals — allocation is forbidden)
__device__ float    g_cqk_pro[NB * HB];
__device__ float    g_u[NB * HB];
__device__ float    g_c[NB];
__device__ unsigned g_cntU, g_done;

__device__ __forceinline__ unsigned ld_acq(const unsigned* p) {
    unsigned v;
    asm volatile("ld.global.acquire.gpu.u32 %0, [%1];" : "=r"(v) : "l"(p));
    return v;
}

// ---------------------------------------------------------------------------
// Launch 1 (1568 blocks x 256): all gather traffic + A-GEMM. No intra-launch
// dependencies, so the 12 MB gather flood can't stretch any critical chain.
//   blocks [0,768):     big gather shifted_encoded (4 float4 per thread)
//   blocks [768,1536):  A-GEMM  cqk_pro[n,h] = cqk[n,:] . W_cqk[h,:] + b[h]
//                       warp -> (4 h, 1 n); all 8 warps of a block share the
//                       same 4 W rows -> 8x L1 reuse, W L2 traffic ~19 MB.
//   blocks [1536,1568): small gathers (mask, tokens, use)
// ---------------------------------------------------------------------------
#define B1_G0   0
#define B1_A0   768
#define B1_SM0  1536
#define GRID1   1568

__global__ void __launch_bounds__(256) k1_gather_agemm(
    const float* __restrict__ ctx1,
    const float* __restrict__ tku,
    const float* __restrict__ Wcqk,
    const float* __restrict__ bcqk,
    const float* __restrict__ pe0,
    const float* __restrict__ pe1,
    const int*   __restrict__ pm,
    const int*   __restrict__ pt,
    const int*   __restrict__ label,
    float* __restrict__ cqkp,
    float* __restrict__ out)
{
    const int b   = blockIdx.x;
    const int tid = threadIdx.x;

    if (b < B1_A0) {
        // ---- big gather: 786432 float4; block covers 1024, thread does 4
        const int n     = b / 24;             // 24 blocks per n
        const int chunk = b % 24;
        const float4* src = (const float4*)(pe0 + ((size_t)n * KB + label[n]) * (size_t)TB * HB);
        float4* dst = (float4*)(out + OFF_ENC + (size_t)n * TB * HB);
        const int i0 = chunk * 1024 + tid;
#pragma unroll
        for (int j = 0; j < 4; j++)
            dst[i0 + j * 256] = src[i0 + j * 256];

    } else if (b < B1_SM0) {
        // ---- A-GEMM
        const int wid  = tid >> 5;
        const int lane = tid & 31;
        const int gw   = (b - B1_A0) * 8 + wid;  // 0..6143
        const int hg   = gw >> 5;                // same for whole block
        const int n    = gw & 31;
        const int h0   = hg * 4;

        float4 a[12];
        const float4* arow0 = (const float4*)(ctx1 + (size_t)n * 3 * HB + 2 * HB);
        const float4* arow1 = (const float4*)(tku  + (size_t)n * HB);
#pragma unroll
        for (int i = 0; i < 6; i++) a[i]     = arow0[i * 32 + lane];
#pragma unroll
        for (int i = 0; i < 6; i++) a[i + 6] = arow1[i * 32 + lane];

        float acc[4];
#pragma unroll
        for (int hh = 0; hh < 4; hh++) {
            const float4* w = (const float4*)(Wcqk + (size_t)(h0 + hh) * H2);
            float s = 0.f;
#pragma unroll
            for (int i = 0; i < 12; i++) {
                float4 wv = w[i * 32 + lane];
                s += a[i].x * wv.x + a[i].y * wv.y + a[i].z * wv.z + a[i].w * wv.w;
            }
            acc[hh] = s;
        }
#pragma unroll
        for (int hh = 0; hh < 4; hh++) {
#pragma unroll
            for (int o = 16; o; o >>= 1)
                acc[hh] += __shfl_xor_sync(0xFFFFFFFFu, acc[hh], o);
        }
        if (lane == 0) {
            float* dst = cqkp + (size_t)n * HB + h0;
            dst[0] = acc[0] + bcqk[h0 + 0];
            dst[1] = acc[1] + bcqk[h0 + 1];
            dst[2] = acc[2] + bcqk[h0 + 2];
            dst[3] = acc[3] + bcqk[h0 + 3];
        }
    } else {
        // ---- small gathers
        const int n    = b - B1_SM0;
        const int lab  = label[n];
        const int base = (n * KB + lab) * TB;
        for (int t = tid; t < TB; t += 256) {
            out[OFF_MASK + n * TB + t] = (pm[base + t] != 0) ? 1.f : 0.f;
            out[OFF_IDX  + n * TB + t] = (float)pt[base + t];
        }
        const size_t ub = ((size_t)n * KB + lab) * HB;
        for (int h = tid; h < HB; h += 256)
            out[OFF_USE + n * HB + h] = pe1[ub + h];
    }
}

// ---------------------------------------------------------------------------
// Launch 2 (225 blocks x 256): the dependency chain, with a CLEAN memory
// system (gather already done).
//   blocks [0,96):   u[n,h] = sum_g cqkp[n,g] * Wk[g,h]
//   block  96:       c[n] = bk . cqkp[n,:]
//   blocks [97,225): score — prefetch pe1 row into registers, THEN spin on
//                    the 97 producers, then dot with u.
// ---------------------------------------------------------------------------
#define B2_C    96
#define B2_S0   97
#define GRID2   225
#define N_PROD  (B2_C + 1)   // 96 u blocks + 1 c block

__global__ void __launch_bounds__(256) k2_chain(
    const float* __restrict__ cqkp,
    const float* __restrict__ Wk,
    const float* __restrict__ bk,
    const float* __restrict__ pe1,
    const int*   __restrict__ ckm,
    float* __restrict__ out)
{
    const int b    = blockIdx.x;
    const int tid  = threadIdx.x;
    const int wid  = tid >> 5;
    const int lane = tid & 31;

    if (b < B2_C) {
        // ---- u-GEMM: warp -> (htile, n); htile constant per block (W reuse)
        const int gw    = b * 8 + wid;        // 0..767
        const int htile = gw >> 5;            // same for whole block
        const int n     = gw & 31;
        const int h     = htile * 32 + lane;
        const float* wcol = Wk + h;
        const float* cr   = cqkp + (size_t)n * HB;

        float acc0 = 0.f, acc1 = 0.f, acc2 = 0.f, acc3 = 0.f;
        for (int g0 = 0; g0 < HB; g0 += 32) {
            float cg = cr[g0 + lane];
#pragma unroll
            for (int j = 0; j < 32; j += 4) {
                acc0 += __shfl_sync(0xFFFFFFFFu, cg, j + 0) * wcol[(size_t)(g0 + j + 0) * HB];
                acc1 += __shfl_sync(0xFFFFFFFFu, cg, j + 1) * wcol[(size_t)(g0 + j + 1) * HB];
                acc2 += __shfl_sync(0xFFFFFFFFu, cg, j + 2) * wcol[(size_t)(g0 + j + 2) * HB];
                acc3 += __shfl_sync(0xFFFFFFFFu, cg, j + 3) * wcol[(size_t)(g0 + j + 3) * HB];
            }
        }
        g_u[(size_t)n * HB + h] = (acc0 + acc1) + (acc2 + acc3);

        __threadfence();
        __syncthreads();
        if (tid == 0) atomicAdd(&g_cntU, 1u);

    } else if (b == B2_C) {
        // ---- c[n] = bk . cqkp[n,:]
#pragma unroll
        for (int r = 0; r < 4; r++) {
            const int n = wid + r * 8;
            const float4* cc  = (const float4*)(cqkp + (size_t)n * HB);
            const float4* bb4 = (const float4*)bk;
            float s = 0.f;
#pragma unroll
            for (int i = 0; i < 6; i++) {
                float4 x = cc[i * 32 + lane];
                float4 y = bb4[i * 32 + lane];
                s += x.x * y.x + x.y * y.y + x.z * y.z + x.w * y.w;
            }
#pragma unroll
            for (int o = 16; o; o >>= 1) s += __shfl_xor_sync(0xFFFFFFFFu, s, o);
            if (lane == 0) g_c[n] = s;
        }
        __threadfence();
        __syncthreads();
        if (tid == 0) atomicAdd(&g_cntU, 1u);

    } else {
        // ---- score: prefetch pe1 into registers FIRST (overlaps u-GEMM),
        //      then spin, then dot with u.
        const int bb = b - B2_S0;
        const int n  = bb >> 2;
        const int kg = bb & 3;
        const int k  = kg * 8 + wid;

        const float4* p = (const float4*)(pe1 + ((size_t)n * KB + k) * HB);
        float4 a[6];
#pragma unroll
        for (int i = 0; i < 6; i++) a[i] = p[i * 32 + lane];

        const int mask_v = ckm[n * KB + k];

        if (tid == 0) {
            while (ld_acq(&g_cntU) < (unsigned)N_PROD) __nanosleep(32);
        }
        __syncthreads();

        const float4* uu = (const float4*)(g_u + (size_t)n * HB);
        float s = 0.f;
#pragma unroll
        for (int i = 0; i < 6; i++) {
            float4 q = uu[i * 32 + lane];
            s += a[i].x * q.x + a[i].y * q.y + a[i].z * q.z + a[i].w * q.w;
        }
#pragma unroll
        for (int o = 16; o; o >>= 1) s += __shfl_xor_sync(0xFFFFFFFFu, s, o);
        if (lane == 0)
            out[OFF_SCORE + n * KB + k] = (mask_v != 0) ? (s + g_c[n]) : -1e20f;
    }

    // ---- replay-safe reset: last block out clears the counters
    __syncthreads();
    if (tid == 0) {
        unsigned v = atomicAdd(&g_done, 1u);
        if (v == (unsigned)(GRID2 - 1)) {
            g_cntU = 0u;
            g_done = 0u;
            __threadfence();
        }
    }
}

extern "C" void kernel_launch(void* const* d_in, const int* in_sizes, int n_in,
                              void* d_out, int out_size)
{
    const float* ctx1 = (const float*)d_in[0];
    const float* tku  = (const float*)d_in[1];
    const float* pe0  = (const float*)d_in[2];
    const float* pe1  = (const float*)d_in[3];
    const int*   pm   = (const int*)d_in[4];
    const int*   ckm  = (const int*)d_in[5];
    const int*   lab  = (const int*)d_in[6];
    const int*   pt   = (const int*)d_in[7];
    const float* Wcqk = (const float*)d_in[8];
    const float* bcqk = (const float*)d_in[9];
    const float* Wk   = (const float*)d_in[10];
    const float* bk   = (const float*)d_in[11];

    float* out = (float*)d_out;

    float* d_cqkp; cudaGetSymbolAddress((void**)&d_cqkp, g_cqk_pro);

    k1_gather_agemm<<<GRID1, 256>>>(ctx1, tku, Wcqk, bcqk, pe0, pe1,
                                    pm, pt, lab, d_cqkp, out);
    k2_chain<<<GRID2, 256>>>(d_cqkp, Wk, bk, pe1, ckm, out);
}

// round 8
// speedup vs baseline: 2.7379x; 1.1594x over previous
#include <cuda_runtime.h>
#include <cstdint>

#define NB 32
#define KB 32
#define TB 128
#define HB 768
#define H2 1536

// Output layout (float32, concat of flattened outputs)
#define OFF_SCORE   0
#define OFF_ENC     1024
#define OFF_MASK    3146752
#define OFF_USE     3150848
#define OFF_IDX     3175424

#define USPLIT 8              // g-splits for the u-GEMM
#define GCH    (HB / USPLIT)  // 96 g per split

// Scratch (device globals — allocation is forbidden)
__device__ float    g_cqk_pro[NB * HB];
__device__ float    g_upart[USPLIT][NB][HB];   // u partials
__device__ float    g_c[NB];
__device__ unsigned g_cntU, g_done;

__device__ __forceinline__ unsigned ld_acq(const unsigned* p) {
    unsigned v;
    asm volatile("ld.global.acquire.gpu.u32 %0, [%1];" : "=r"(v) : "l"(p));
    return v;
}

// ---------------------------------------------------------------------------
// Launch 1 (1568 blocks x 256): all independent work.
//   blocks [0,768):     big gather shifted_encoded (4 float4 per thread)
//   blocks [768,1536):  A-GEMM  cqk_pro[n,h] = cqk[n,:] . W_cqk[h,:] + b[h]
//   blocks [1536,1568): small gathers
// ---------------------------------------------------------------------------
#define B1_A0   768
#define B1_SM0  1536
#define GRID1   1568

__global__ void __launch_bounds__(256) k1_gather_agemm(
    const float* __restrict__ ctx1,
    const float* __restrict__ tku,
    const float* __restrict__ Wcqk,
    const float* __restrict__ bcqk,
    const float* __restrict__ pe0,
    const float* __restrict__ pe1,
    const int*   __restrict__ pm,
    const int*   __restrict__ pt,
    const int*   __restrict__ label,
    float* __restrict__ cqkp,
    float* __restrict__ out)
{
    const int b   = blockIdx.x;
    const int tid = threadIdx.x;

    if (b < B1_A0) {
        // ---- big gather
        const int n     = b / 24;
        const int chunk = b % 24;
        const float4* src = (const float4*)(pe0 + ((size_t)n * KB + label[n]) * (size_t)TB * HB);
        float4* dst = (float4*)(out + OFF_ENC + (size_t)n * TB * HB);
        const int i0 = chunk * 1024 + tid;
#pragma unroll
        for (int j = 0; j < 4; j++)
            dst[i0 + j * 256] = src[i0 + j * 256];

    } else if (b < B1_SM0) {
        // ---- A-GEMM: warp -> (4 h, 1 n); block shares the same 4 W rows
        const int wid  = tid >> 5;
        const int lane = tid & 31;
        const int gw   = (b - B1_A0) * 8 + wid;
        const int hg   = gw >> 5;
        const int n    = gw & 31;
        const int h0   = hg * 4;

        float4 a[12];
        const float4* arow0 = (const float4*)(ctx1 + (size_t)n * 3 * HB + 2 * HB);
        const float4* arow1 = (const float4*)(tku  + (size_t)n * HB);
#pragma unroll
        for (int i = 0; i < 6; i++) a[i]     = arow0[i * 32 + lane];
#pragma unroll
        for (int i = 0; i < 6; i++) a[i + 6] = arow1[i * 32 + lane];

        float acc[4];
#pragma unroll
        for (int hh = 0; hh < 4; hh++) {
            const float4* w = (const float4*)(Wcqk + (size_t)(h0 + hh) * H2);
            float s = 0.f;
#pragma unroll
            for (int i = 0; i < 12; i++) {
                float4 wv = w[i * 32 + lane];
                s += a[i].x * wv.x + a[i].y * wv.y + a[i].z * wv.z + a[i].w * wv.w;
            }
            acc[hh] = s;
        }
#pragma unroll
        for (int hh = 0; hh < 4; hh++) {
#pragma unroll
            for (int o = 16; o; o >>= 1)
                acc[hh] += __shfl_xor_sync(0xFFFFFFFFu, acc[hh], o);
        }
        if (lane == 0) {
            float* dst = cqkp + (size_t)n * HB + h0;
            dst[0] = acc[0] + bcqk[h0 + 0];
            dst[1] = acc[1] + bcqk[h0 + 1];
            dst[2] = acc[2] + bcqk[h0 + 2];
            dst[3] = acc[3] + bcqk[h0 + 3];
        }
    } else {
        // ---- small gathers
        const int n    = b - B1_SM0;
        const int lab  = label[n];
        const int base = (n * KB + lab) * TB;
        for (int t = tid; t < TB; t += 256) {
            out[OFF_MASK + n * TB + t] = (pm[base + t] != 0) ? 1.f : 0.f;
            out[OFF_IDX  + n * TB + t] = (float)pt[base + t];
        }
        const size_t ub = ((size_t)n * KB + lab) * HB;
        for (int h = tid; h < HB; h += 256)
            out[OFF_USE + n * HB + h] = pe1[ub + h];
    }
}

// ---------------------------------------------------------------------------
// Launch 2 (897 blocks x 256): dependency chain with split-K u-GEMM.
//   blocks [0,768):   u partials. Block = (htile, split, ngroup); warp ->
//                     (htile, split, one n). Each warp does only GCH=96
//                     Wk line-loads; 768 blocks saturate MLP chip-wide.
//                     All 8 warps of a block read the SAME 96 lines (L1 8x).
//   block  768:       c[n] = bk . cqkp[n,:]
//   blocks [769,897): score — prefetch pe1 rows, spin on 769 producers,
//                     sum 8 partials (L2-hot) and dot with pe1.
// ---------------------------------------------------------------------------
#define B2_C    768
#define B2_S0   769
#define GRID2   897
#define N_PROD  (B2_C + 1)    // 768 u blocks + 1 c block

__global__ void __launch_bounds__(256) k2_chain(
    const float* __restrict__ cqkp,
    const float* __restrict__ Wk,
    const float* __restrict__ bk,
    const float* __restrict__ pe1,
    const int*   __restrict__ ckm,
    float* __restrict__ out)
{
    const int b    = blockIdx.x;
    const int tid  = threadIdx.x;
    const int wid  = tid >> 5;
    const int lane = tid & 31;

    if (b < B2_C) {
        // ---- u partial: b = htile*32 + split*4 + ngroup
        const int htile  = b >> 5;            // 0..23  (same for block)
        const int split  = (b >> 2) & 7;      // 0..7   (same for block)
        const int ngroup = b & 3;             // 0..3   (same for block)
        const int n      = ngroup * 8 + wid;  // warp's n
        const int h      = htile * 32 + lane;
        const int g0     = split * GCH;

        const float* wcol = Wk + (size_t)g0 * HB + h;
        const float* cr   = cqkp + (size_t)n * HB + g0;

        float acc0 = 0.f, acc1 = 0.f, acc2 = 0.f, acc3 = 0.f;
#pragma unroll
        for (int gb = 0; gb < GCH; gb += 32) {
            float cg = cr[gb + lane];
            const float* wbase = wcol + (size_t)gb * HB;
#pragma unroll
            for (int j = 0; j < 32; j += 4) {
                acc0 += __shfl_sync(0xFFFFFFFFu, cg, j + 0) * wbase[(size_t)(j + 0) * HB];
                acc1 += __shfl_sync(0xFFFFFFFFu, cg, j + 1) * wbase[(size_t)(j + 1) * HB];
                acc2 += __shfl_sync(0xFFFFFFFFu, cg, j + 2) * wbase[(size_t)(j + 2) * HB];
                acc3 += __shfl_sync(0xFFFFFFFFu, cg, j + 3) * wbase[(size_t)(j + 3) * HB];
            }
        }
        g_upart[split][n][h] = (acc0 + acc1) + (acc2 + acc3);

        __threadfence();
        __syncthreads();
        if (tid == 0) atomicAdd(&g_cntU, 1u);

    } else if (b == B2_C) {
        // ---- c[n] = bk . cqkp[n,:]
#pragma unroll
        for (int r = 0; r < 4; r++) {
            const int n = wid + r * 8;
            const float4* cc  = (const float4*)(cqkp + (size_t)n * HB);
            const float4* bb4 = (const float4*)bk;
            float s = 0.f;
#pragma unroll
            for (int i = 0; i < 6; i++) {
                float4 x = cc[i * 32 + lane];
                float4 y = bb4[i * 32 + lane];
                s += x.x * y.x + x.y * y.y + x.z * y.z + x.w * y.w;
            }
#pragma unroll
            for (int o = 16; o; o >>= 1) s += __shfl_xor_sync(0xFFFFFFFFu, s, o);
            if (lane == 0) g_c[n] = s;
        }
        __threadfence();
        __syncthreads();
        if (tid == 0) atomicAdd(&g_cntU, 1u);

    } else {
        // ---- score: prefetch pe1 into regs, spin, then sum partials + dot
        const int bb = b - B2_S0;
        const int n  = bb >> 2;
        const int kg = bb & 3;
        const int k  = kg * 8 + wid;

        const float4* p = (const float4*)(pe1 + ((size_t)n * KB + k) * HB);
        float4 a[6];
#pragma unroll
        for (int i = 0; i < 6; i++) a[i] = p[i * 32 + lane];

        const int mask_v = ckm[n * KB + k];

        if (tid == 0) {
            while (ld_acq(&g_cntU) < (unsigned)N_PROD) __nanosleep(32);
        }
        __syncthreads();

        float s = 0.f;
#pragma unroll
        for (int i = 0; i < 6; i++) {
            const int hb4 = i * 32 + lane;      // float4 index into u row
            float4 q0 = *(const float4*)(&g_upart[0][n][hb4 * 4]);
#pragma unroll
            for (int sp = 1; sp < USPLIT; sp++) {
                float4 qs = *(const float4*)(&g_upart[sp][n][hb4 * 4]);
                q0.x += qs.x; q0.y += qs.y; q0.z += qs.z; q0.w += qs.w;
            }
            s += a[i].x * q0.x + a[i].y * q0.y + a[i].z * q0.z + a[i].w * q0.w;
        }
#pragma unroll
        for (int o = 16; o; o >>= 1) s += __shfl_xor_sync(0xFFFFFFFFu, s, o);
        if (lane == 0)
            out[OFF_SCORE + n * KB + k] = (mask_v != 0) ? (s + g_c[n]) : -1e20f;
    }

    // ---- replay-safe reset: last block out clears the counters
    __syncthreads();
    if (tid == 0) {
        unsigned v = atomicAdd(&g_done, 1u);
        if (v == (unsigned)(GRID2 - 1)) {
            g_cntU = 0u;
            g_done = 0u;
            __threadfence();
        }
    }
}

extern "C" void kernel_launch(void* const* d_in, const int* in_sizes, int n_in,
                              void* d_out, int out_size)
{
    const float* ctx1 = (const float*)d_in[0];
    const float* tku  = (const float*)d_in[1];
    const float* pe0  = (const float*)d_in[2];
    const float* pe1  = (const float*)d_in[3];
    const int*   pm   = (const int*)d_in[4];
    const int*   ckm  = (const int*)d_in[5];
    const int*   lab  = (const int*)d_in[6];
    const int*   pt   = (const int*)d_in[7];
    const float* Wcqk = (const float*)d_in[8];
    const float* bcqk = (const float*)d_in[9];
    const float* Wk   = (const float*)d_in[10];
    const float* bk   = (const float*)d_in[11];

    float* out = (float*)d_out;

    float* d_cqkp; cudaGetSymbolAddress((void**)&d_cqkp, g_cqk_pro);

    k1_gather_agemm<<<GRID1, 256>>>(ctx1, tku, Wcqk, bcqk, pe0, pe1,
                                    pm, pt, lab, d_cqkp, out);
    k2_chain<<<GRID2, 256>>>(d_cqkp, Wk, bk, pe1, ckm, out);
}

// round 9
// speedup vs baseline: 2.9617x; 1.0817x over previous
#include <cuda_runtime.h>
#include <cstdint>

#define NB 32
#define KB 32
#define TB 128
#define HB 768
#define H2 1536

// Output layout (float32, concat of flattened outputs)
#define OFF_SCORE   0
#define OFF_ENC     1024
#define OFF_MASK    3146752
#define OFF_USE     3150848
#define OFF_IDX     3175424

#define USPLIT 8              // g-splits for the u-GEMM
#define GCH    (HB / USPLIT)  // 96 g per split

// Scratch (device globals — allocation is forbidden)
__device__ float    g_cqk_pro[NB * HB];
__device__ float    g_upart[USPLIT][NB][HB];   // u partials
__device__ float    g_c[NB];
__device__ unsigned g_cntU, g_done;

__device__ __forceinline__ unsigned ld_acq(const unsigned* p) {
    unsigned v;
    asm volatile("ld.global.acquire.gpu.u32 %0, [%1];" : "=r"(v) : "l"(p));
    return v;
}

// ---------------------------------------------------------------------------
// Launch 1 (1568 blocks x 256): all independent work.
//   blocks [0,768):     big gather shifted_encoded (4 float4 per thread)
//   blocks [768,1536):  A-GEMM  cqk_pro[n,h] = cqk[n,:] . W_cqk[h,:] + b[h]
//   blocks [1536,1568): small gathers
// ---------------------------------------------------------------------------
#define B1_A0   768
#define B1_SM0  1536
#define GRID1   1568

__global__ void __launch_bounds__(256) k1_gather_agemm(
    const float* __restrict__ ctx1,
    const float* __restrict__ tku,
    const float* __restrict__ Wcqk,
    const float* __restrict__ bcqk,
    const float* __restrict__ pe0,
    const float* __restrict__ pe1,
    const int*   __restrict__ pm,
    const int*   __restrict__ pt,
    const int*   __restrict__ label,
    float* __restrict__ cqkp,
    float* __restrict__ out)
{
    const int b   = blockIdx.x;
    const int tid = threadIdx.x;

    if (b < B1_A0) {
        // ---- big gather
        const int n     = b / 24;
        const int chunk = b % 24;
        const float4* src = (const float4*)(pe0 + ((size_t)n * KB + label[n]) * (size_t)TB * HB);
        float4* dst = (float4*)(out + OFF_ENC + (size_t)n * TB * HB);
        const int i0 = chunk * 1024 + tid;
#pragma unroll
        for (int j = 0; j < 4; j++)
            dst[i0 + j * 256] = src[i0 + j * 256];

    } else if (b < B1_SM0) {
        // ---- A-GEMM: warp -> (4 h, 1 n); block shares the same 4 W rows
        const int wid  = tid >> 5;
        const int lane = tid & 31;
        const int gw   = (b - B1_A0) * 8 + wid;
        const int hg   = gw >> 5;
        const int n    = gw & 31;
        const int h0   = hg * 4;

        float4 a[12];
        const float4* arow0 = (const float4*)(ctx1 + (size_t)n * 3 * HB + 2 * HB);
        const float4* arow1 = (const float4*)(tku  + (size_t)n * HB);
#pragma unroll
        for (int i = 0; i < 6; i++) a[i]     = arow0[i * 32 + lane];
#pragma unroll
        for (int i = 0; i < 6; i++) a[i + 6] = arow1[i * 32 + lane];

        float acc[4];
#pragma unroll
        for (int hh = 0; hh < 4; hh++) {
            const float4* w = (const float4*)(Wcqk + (size_t)(h0 + hh) * H2);
            float s = 0.f;
#pragma unroll
            for (int i = 0; i < 12; i++) {
                float4 wv = w[i * 32 + lane];
                s += a[i].x * wv.x + a[i].y * wv.y + a[i].z * wv.z + a[i].w * wv.w;
            }
            acc[hh] = s;
        }
#pragma unroll
        for (int hh = 0; hh < 4; hh++) {
#pragma unroll
            for (int o = 16; o; o >>= 1)
                acc[hh] += __shfl_xor_sync(0xFFFFFFFFu, acc[hh], o);
        }
        if (lane == 0) {
            float* dst = cqkp + (size_t)n * HB + h0;
            dst[0] = acc[0] + bcqk[h0 + 0];
            dst[1] = acc[1] + bcqk[h0 + 1];
            dst[2] = acc[2] + bcqk[h0 + 2];
            dst[3] = acc[3] + bcqk[h0 + 3];
        }
    } else {
        // ---- small gathers
        const int n    = b - B1_SM0;
        const int lab  = label[n];
        const int base = (n * KB + lab) * TB;
        for (int t = tid; t < TB; t += 256) {
            out[OFF_MASK + n * TB + t] = (pm[base + t] != 0) ? 1.f : 0.f;
            out[OFF_IDX  + n * TB + t] = (float)pt[base + t];
        }
        const size_t ub = ((size_t)n * KB + lab) * HB;
        for (int h = tid; h < HB; h += 256)
            out[OFF_USE + n * HB + h] = pe1[ub + h];
    }
}

// ---------------------------------------------------------------------------
// Launch 2 (321 blocks x 256): dependency chain, dense split-K u-GEMM.
//   blocks [0,192):   u partials. Warp = (htile of 128 h via float4, split,
//                     one n). 96 float4 Wk loads per warp; all 8 warps of a
//                     block (8 n) share the same Wk lines (L1 8x). Single
//                     wave (192 blocks << capacity).
//   block  192:       c[n] = bk . cqkp[n,:]
//   blocks [193,321): score — prefetch pe1 rows, spin on 193 producers,
//                     sum 8 partials (L2-hot) and dot with pe1.
// ---------------------------------------------------------------------------
#define B2_U    192
#define B2_C    192
#define B2_S0   193
#define GRID2   321
#define N_PROD  (B2_U + 1)    // 192 u blocks + 1 c block

__global__ void __launch_bounds__(256) k2_chain(
    const float* __restrict__ cqkp,
    const float* __restrict__ Wk,
    const float* __restrict__ bk,
    const float* __restrict__ pe1,
    const int*   __restrict__ ckm,
    float* __restrict__ out)
{
    const int b    = blockIdx.x;
    const int tid  = threadIdx.x;
    const int wid  = tid >> 5;
    const int lane = tid & 31;

    if (b < B2_U) {
        // ---- u partial: b = htile*32 + split*4 + ngroup  (htile 0..5)
        const int htile = b >> 5;             // same for block
        const int rem   = b & 31;
        const int split = rem >> 2;           // 0..7, same for block
        const int ng    = rem & 3;
        const int n     = ng * 8 + wid;       // warp's n
        const int h0    = htile * 128 + lane * 4;
        const int g0    = split * GCH;

        const float4* wrow = (const float4*)(Wk + (size_t)g0 * HB + h0);
        const float*  cr   = cqkp + (size_t)n * HB + g0;

        float4 acc0 = {0.f, 0.f, 0.f, 0.f};
        float4 acc1 = {0.f, 0.f, 0.f, 0.f};

#pragma unroll
        for (int gb = 0; gb < GCH; gb += 32) {
            float cg = cr[gb + lane];
            const float4* wb = wrow + (size_t)gb * (HB / 4);
#pragma unroll
            for (int j = 0; j < 32; j += 2) {
                float c0 = __shfl_sync(0xFFFFFFFFu, cg, j);
                float c1 = __shfl_sync(0xFFFFFFFFu, cg, j + 1);
                float4 w0 = wb[(size_t)j * (HB / 4)];
                float4 w1 = wb[(size_t)(j + 1) * (HB / 4)];
                acc0.x += c0 * w0.x; acc0.y += c0 * w0.y;
                acc0.z += c0 * w0.z; acc0.w += c0 * w0.w;
                acc1.x += c1 * w1.x; acc1.y += c1 * w1.y;
                acc1.z += c1 * w1.z; acc1.w += c1 * w1.w;
            }
        }
        float4 r;
        r.x = acc0.x + acc1.x; r.y = acc0.y + acc1.y;
        r.z = acc0.z + acc1.z; r.w = acc0.w + acc1.w;
        *(float4*)(&g_upart[split][n][h0]) = r;

        __threadfence();
        __syncthreads();
        if (tid == 0) atomicAdd(&g_cntU, 1u);

    } else if (b == B2_C) {
        // ---- c[n] = bk . cqkp[n,:]
#pragma unroll
        for (int r = 0; r < 4; r++) {
            const int n = wid + r * 8;
            const float4* cc  = (const float4*)(cqkp + (size_t)n * HB);
            const float4* bb4 = (const float4*)bk;
            float s = 0.f;
#pragma unroll
            for (int i = 0; i < 6; i++) {
                float4 x = cc[i * 32 + lane];
                float4 y = bb4[i * 32 + lane];
                s += x.x * y.x + x.y * y.y + x.z * y.z + x.w * y.w;
            }
#pragma unroll
            for (int o = 16; o; o >>= 1) s += __shfl_xor_sync(0xFFFFFFFFu, s, o);
            if (lane == 0) g_c[n] = s;
        }
        __threadfence();
        __syncthreads();
        if (tid == 0) atomicAdd(&g_cntU, 1u);

    } else {
        // ---- score: prefetch pe1 into regs, spin, then sum partials + dot
        const int bb = b - B2_S0;
        const int n  = bb >> 2;
        const int kg = bb & 3;
        const int k  = kg * 8 + wid;

        const float4* p = (const float4*)(pe1 + ((size_t)n * KB + k) * HB);
        float4 a[6];
#pragma unroll
        for (int i = 0; i < 6; i++) a[i] = p[i * 32 + lane];

        const int mask_v = ckm[n * KB + k];

        if (tid == 0) {
            while (ld_acq(&g_cntU) < (unsigned)N_PROD) __nanosleep(32);
        }
        __syncthreads();

        float s = 0.f;
#pragma unroll
        for (int i = 0; i < 6; i++) {
            const int hh = (i * 32 + lane) * 4;
            float4 q0 = *(const float4*)(&g_upart[0][n][hh]);
#pragma unroll
            for (int sp = 1; sp < USPLIT; sp++) {
                float4 qs = *(const float4*)(&g_upart[sp][n][hh]);
                q0.x += qs.x; q0.y += qs.y; q0.z += qs.z; q0.w += qs.w;
            }
            s += a[i].x * q0.x + a[i].y * q0.y + a[i].z * q0.z + a[i].w * q0.w;
        }
#pragma unroll
        for (int o = 16; o; o >>= 1) s += __shfl_xor_sync(0xFFFFFFFFu, s, o);
        if (lane == 0)
            out[OFF_SCORE + n * KB + k] = (mask_v != 0) ? (s + g_c[n]) : -1e20f;
    }

    // ---- replay-safe reset: last block out clears the counters
    __syncthreads();
    if (tid == 0) {
        unsigned v = atomicAdd(&g_done, 1u);
        if (v == (unsigned)(GRID2 - 1)) {
            g_cntU = 0u;
            g_done = 0u;
            __threadfence();
        }
    }
}

extern "C" void kernel_launch(void* const* d_in, const int* in_sizes, int n_in,
                              void* d_out, int out_size)
{
    const float* ctx1 = (const float*)d_in[0];
    const float* tku  = (const float*)d_in[1];
    const float* pe0  = (const float*)d_in[2];
    const float* pe1  = (const float*)d_in[3];
    const int*   pm   = (const int*)d_in[4];
    const int*   ckm  = (const int*)d_in[5];
    const int*   lab  = (const int*)d_in[6];
    const int*   pt   = (const int*)d_in[7];
    const float* Wcqk = (const float*)d_in[8];
    const float* bcqk = (const float*)d_in[9];
    const float* Wk   = (const float*)d_in[10];
    const float* bk   = (const float*)d_in[11];

    float* out = (float*)d_out;

    float* d_cqkp; cudaGetSymbolAddress((void**)&d_cqkp, g_cqk_pro);

    k1_gather_agemm<<<GRID1, 256>>>(ctx1, tku, Wcqk, bcqk, pe0, pe1,
                                    pm, pt, lab, d_cqkp, out);
    k2_chain<<<GRID2, 256>>>(d_cqkp, Wk, bk, pe1, ckm, out);
}